// round 10
// baseline (speedup 1.0000x reference)
#include <cuda_runtime.h>
#include <cuda_bf16.h>
#include <math.h>
#include <stdint.h>

#define NBINS 128
#define NFREQ 64
#define NKERN 3
#define MLPH  64
#define KPB   28   // keys per block -> grid 293; 2 blocks/SM
#define TPB   256
#define MAXBLK 293 // ceil(8192/28)

typedef unsigned long long ull;

// Planar coefficient table: g_C[f][coord][bin], coord 0..8 =
//   [A0, A1c, A1s, A2c, A2s, A3c, A3s, A4c, A4s]
__device__ float4 g_C4[NFREQ * 9 * NBINS / 4];

// Feature table: [f][blk][j][kq] -> float4 {mag, 2*cos1, x, y}; 64B contiguous per (f,blk,j)
__device__ float4 g_X[NFREQ * MAXBLK * 7 * 4];

__device__ __forceinline__ void fma2(ull& acc, ull a, ull b) {
    asm("fma.rn.f32x2 %0, %1, %2, %0;" : "+l"(acc) : "l"(a), "l"(b));
}
__device__ __forceinline__ ull dup2(float v) {
    ull r;
    asm("mov.b64 %0, {%1, %1};" : "=l"(r) : "f"(v));
    return r;
}
__device__ __forceinline__ float2 unpack2(ull v) {
    float2 r;
    asm("mov.b64 {%0, %1}, %2;" : "=f"(r.x), "=f"(r.y) : "l"(v));
    return r;
}

__global__ void precompute_fourier(const float* __restrict__ mu,
                                   const float* __restrict__ kappa,
                                   const float* __restrict__ weight,
                                   const float* __restrict__ ref_angles) {
    int idx = blockIdx.x * blockDim.x + threadIdx.x;
    if (idx >= NBINS * NFREQ) return;
    int b = idx / NFREQ;
    int f = idx % NFREQ;
    float C[9];
    #pragma unroll
    for (int i = 0; i < 9; i++) C[i] = 0.f;

    #pragma unroll
    for (int m = 0; m < NKERN; m++) {
        int off = (b * NFREQ + f) * NKERN + m;
        float kp = kappa[off];
        float w  = weight[off];
        float me = mu[off] + ref_angles[f];
        float h  = 0.5f * kp;
        float h2 = h * h;
        float ek = __expf(-kp);
        float I[5];
        float hk = 1.f, kfact = 1.f;
        #pragma unroll
        for (int kk = 0; kk < 5; kk++) {
            if (kk > 0) { hk *= h; kfact *= (float)kk; }
            float term = hk / kfact;
            float s = term;
            #pragma unroll
            for (int t = 1; t <= 8; t++) {
                term *= h2 / ((float)t * (float)(t + kk));
                s += term;
            }
            I[kk] = s;
        }
        float cm, sm;
        __sincosf(me, &sm, &cm);
        float wek = w * ek;
        C[0] += wek * I[0];
        float ck = cm, sk = sm;
        #pragma unroll
        for (int kk = 1; kk <= 4; kk++) {
            float g = 2.f * wek * I[kk];
            C[2 * kk - 1] += g * ck;
            C[2 * kk]     += g * sk;
            float cn = ck * cm - sk * sm;
            float sn = sk * cm + ck * sm;
            ck = cn; sk = sn;
        }
    }
    float* gC = (float*)g_C4;
    #pragma unroll
    for (int c = 0; c < 9; c++)
        gC[(f * 9 + c) * NBINS + b] = C[c];
}

// Build features once chip-wide: g_X[f][blk][j][kq] = {mag, 2*cos1, x, y}
__global__ void build_X(const float2* __restrict__ K2, int n, int nblk) {
    int idx = blockIdx.x * blockDim.x + threadIdx.x;
    int total = NFREQ * nblk * 28;
    if (idx >= total) return;
    int kq  = idx & 3;
    int j   = (idx >> 2) % 7;
    int rem = idx / 28;
    int blk = rem % nblk;
    int f   = rem / nblk;
    int key = blk * KPB + kq * 7 + j;
    if (key >= n) key = n - 1;
    float2 v = K2[key * NFREQ + f];
    float r2 = fmaf(v.x, v.x, v.y * v.y);
    r2 = fmaxf(r2, 1e-30f);
    float rinv = rsqrtf(r2);
    float mag = r2 * rinv;
    float c1x2 = 2.f * v.x * rinv;
    g_X[((size_t)f * nblk + blk) * 28 + j * 4 + kq] = make_float4(mag, c1x2, v.x, v.y);
}

// dynamic smem (floats):
//   sl[28*128] @ 0   | w1T[128*66] | h[28*64] | b1w2[128]
#define OFF_U    (KPB * NBINS)                 // 3584
#define OFF_H    (OFF_U + 128 * 66)
#define OFF_B1W2 (OFF_H + KPB * MLPH)
#define SMEM_BYTES ((OFF_B1W2 + 2 * MLPH) * 4)

__global__ __launch_bounds__(TPB, 2)
void key_pruning_main(const int*   __restrict__ pos,
                      const float* __restrict__ bias,
                      const float* __restrict__ W1,      // [64][128]
                      const float* __restrict__ b1,
                      const float* __restrict__ W2,
                      const float* __restrict__ b2,
                      const float* __restrict__ araw,
                      float*       __restrict__ out,
                      int n) {
    extern __shared__ float sm[];

    const int tid  = threadIdx.x;
    const int warp = tid >> 5;
    const int lane = tid & 31;
    const int key0 = blockIdx.x * KPB;
    const int nblk = gridDim.x;

    // ---- Phase 2: logits GEMM. warp = 28 keys x 32 bins; f split across warp-halves.
    //      Thread: 7 keys x 4 bins. X via LDG (dedup'd), C via LDG. ----
    const int fbase = (warp >= 4) ? 32 : 0;
    const int wb    = (warp & 3) * 32;
    const int kq    = lane >> 3;
    const int b0    = wb + (lane & 7) * 4;   // thread bins b0..b0+3
    const int kbase = kq * 7;

    ull acc[14];
    #pragma unroll
    for (int i = 0; i < 14; i++) acc[i] = 0ull;

    const float* gC = (const float*)g_C4;

    for (int fo = 0; fo < 32; fo++) {
        int f = fbase + fo;
        const float4* Xr = g_X + ((size_t)f * nblk + blockIdx.x) * 28 + kq;
        const float* Cf = gC + f * 9 * NBINS + b0;
        ulonglong2 Cc[9];
        #pragma unroll
        for (int c = 0; c < 9; c++)
            Cc[c] = *(const ulonglong2*)(Cf + c * NBINS);
        #pragma unroll
        for (int j = 0; j < 7; j++) {
            float4 x = __ldg(&Xr[j * 4]);
            float xs0 = x.x;                        // m
            float c1x2 = x.y;                       // 2*cos1
            float xs1 = x.z;                        // m*cos1
            float xs2 = x.w;                        // m*sin1
            float xs3 = fmaf(c1x2, xs1, -xs0);      // m*cos2
            float xs4 = c1x2 * xs2;                 // m*sin2
            float xs5 = fmaf(c1x2, xs3, -xs1);      // m*cos3
            float xs6 = fmaf(c1x2, xs4, -xs2);      // m*sin3
            float xs7 = fmaf(c1x2, xs5, -xs3);      // m*cos4
            float xs8 = fmaf(c1x2, xs6, -xs4);      // m*sin4
            ull* a = &acc[2 * j];
            #define STEP(c, v) { ull d = dup2(v); fma2(a[0], d, Cc[c].x); fma2(a[1], d, Cc[c].y); }
            STEP(0, xs0) STEP(1, xs1) STEP(2, xs2) STEP(3, xs3) STEP(4, xs4)
            STEP(5, xs5) STEP(6, xs6) STEP(7, xs7) STEP(8, xs8)
            #undef STEP
        }
    }

    // f-split reduction into sl (low-f warps write with bias; high-f warps add)
    float4 bias4 = *(const float4*)&bias[b0];
    if (warp < 4) {
        #pragma unroll
        for (int j = 0; j < 7; j++) {
            float2 p0 = unpack2(acc[2 * j]);
            float2 p1 = unpack2(acc[2 * j + 1]);
            float4 o = make_float4(p0.x + bias4.x, p0.y + bias4.y,
                                   p1.x + bias4.z, p1.y + bias4.w);
            *(float4*)&sm[(kbase + j) * NBINS + b0] = o;
        }
    }
    __syncthreads();
    if (warp >= 4) {
        #pragma unroll
        for (int j = 0; j < 7; j++) {
            float2 p0 = unpack2(acc[2 * j]);
            float2 p1 = unpack2(acc[2 * j + 1]);
            float4 cur = *(float4*)&sm[(kbase + j) * NBINS + b0];
            cur.x += p0.x; cur.y += p0.y; cur.z += p1.x; cur.w += p1.y;
            *(float4*)&sm[(kbase + j) * NBINS + b0] = cur;
        }
    } else {
        // ---- Phase 3 (overlapped): stage transposed W1 [k][h], stride 66 ----
        for (int i = tid; i < MLPH * NBINS; i += 128) {
            int h = i >> 7;
            int k = i & 127;
            sm[OFF_U + k * 66 + h] = W1[i];
        }
        if (tid < MLPH) {
            sm[OFF_B1W2 + tid]        = b1[tid];
            sm[OFF_B1W2 + MLPH + tid] = W2[tid];
        }
    }
    __syncthreads();

    // ---- Phase 4: MLP layer 1 on 128 threads: 7 keys x 2 hidden per thread ----
    if (tid < 128) {
        int pkq = tid >> 5;            // key quarter (uniform per warp)
        int hb  = (tid & 31) * 2;      // hidden pair
        float a[7][2];
        #pragma unroll
        for (int j = 0; j < 7; j++) { a[j][0] = 0.f; a[j][1] = 0.f; }
        #pragma unroll 4
        for (int k = 0; k < NBINS; k++) {
            float2 w = *(const float2*)&sm[OFF_U + k * 66 + hb];
            #pragma unroll
            for (int j = 0; j < 7; j++) {
                float l = sm[(pkq * 7 + j) * NBINS + k];
                a[j][0] = fmaf(l, w.x, a[j][0]);
                a[j][1] = fmaf(l, w.y, a[j][1]);
            }
        }
        float bb0 = sm[OFF_B1W2 + hb],        bb1 = sm[OFF_B1W2 + hb + 1];
        float w20 = sm[OFF_B1W2 + MLPH + hb], w21 = sm[OFF_B1W2 + MLPH + hb + 1];
        #pragma unroll
        for (int j = 0; j < 7; j++) {
            float h0 = fmaxf(a[j][0] + bb0, 0.f) * w20;
            float h1 = fmaxf(a[j][1] + bb1, 0.f) * w21;
            *(float2*)&sm[OFF_H + (pkq * 7 + j) * MLPH + hb] = make_float2(h0, h1);
        }
    }
    __syncthreads();

    // ---- Phase 5: reduce, position weight, sigmoid ----
    if (tid < KPB && (key0 + tid) < n) {
        float s = b2[0];
        const float4* hp = (const float4*)&sm[OFF_H + tid * MLPH];
        float s1 = 0.f, s2 = 0.f, s3 = 0.f;
        #pragma unroll
        for (int j = 0; j < MLPH / 4; j++) {
            float4 v = hp[j];
            s += v.x; s1 += v.y; s2 += v.z; s3 += v.w;
        }
        s = (s + s1) + (s2 + s3);

        int p = pos[key0 + tid];
        float lp = log10f(fmaxf((float)p, 1.0f));
        float a0 = log1pf(expf(araw[0]));
        float a1 = log1pf(expf(araw[1]));
        float a2 = log1pf(expf(araw[2]));
        float w;
        if (lp < 3.f)      w = a0;
        else if (lp < 4.f) w = a0 + (a1 - a0) * (lp - 3.f);
        else if (lp < 5.f) w = a1 + (a2 - a1) * (lp - 4.f);
        else               w = a2;

        float z = s * w;
        out[key0 + tid] = 1.f / (1.f + expf(-z));
    }
}

extern "C" void kernel_launch(void* const* d_in, const int* in_sizes, int n_in,
                              void* d_out, int out_size) {
    const float* K      = (const float*)d_in[0];
    const int*   pos    = (const int*)  d_in[1];
    const float* ra     = (const float*)d_in[2];
    const float* mu     = (const float*)d_in[3];
    const float* kappa  = (const float*)d_in[4];
    const float* weight = (const float*)d_in[5];
    const float* bias   = (const float*)d_in[6];
    const float* W1     = (const float*)d_in[7];
    const float* b1     = (const float*)d_in[8];
    const float* W2     = (const float*)d_in[9];
    const float* b2     = (const float*)d_in[10];
    const float* araw   = (const float*)d_in[11];

    int n = in_sizes[1];   // number of keys
    int nblk = (n + KPB - 1) / KPB;
    if (nblk > MAXBLK) nblk = MAXBLK;  // capacity guard (n fixed at 8192 for this problem)

    static int smem_set = 0;
    if (!smem_set) {
        cudaFuncSetAttribute(key_pruning_main,
                             cudaFuncAttributeMaxDynamicSharedMemorySize, SMEM_BYTES);
        smem_set = 1;
    }

    precompute_fourier<<<(NBINS * NFREQ + 127) / 128, 128>>>(mu, kappa, weight, ra);
    build_X<<<(NFREQ * nblk * 28 + 255) / 256, 256>>>((const float2*)K, n, nblk);
    key_pruning_main<<<nblk, TPB, SMEM_BYTES>>>(pos, bias, W1, b1, W2, b2, araw,
                                                (float*)d_out, n);
}

// round 11
// speedup vs baseline: 2.1926x; 2.1926x over previous
#include <cuda_runtime.h>
#include <cuda_bf16.h>
#include <math.h>

#define NBINS 128
#define NFREQ 64
#define NKERN 3
#define MLPH  64
#define KPB   28   // keys per block -> grid 293; 2 blocks/SM
#define TPB   256

typedef unsigned long long ull;

// Planar coefficient table: g_C[f][coord][bin], coord 0..6 =
//   [A0, A1c, A1s, A2c, A2s, A3c, A3s]
// pairing with features [m, mc1, ms1, mc2, ms2, mc3, ms3].
__device__ float4 g_C4[NFREQ * 7 * NBINS / 4];

__device__ __forceinline__ void fma2(ull& acc, ull a, ull b) {
    asm("fma.rn.f32x2 %0, %1, %2, %0;" : "+l"(acc) : "l"(a), "l"(b));
}
__device__ __forceinline__ ull dup2(float v) {
    ull r;
    asm("mov.b64 %0, {%1, %1};" : "=l"(r) : "f"(v));
    return r;
}
__device__ __forceinline__ float2 unpack2(ull v) {
    float2 r;
    asm("mov.b64 {%0, %1}, %2;" : "=f"(r.x), "=f"(r.y) : "l"(v));
    return r;
}

// I_k(kappa) via Horner series in h2 = (kappa/2)^2 with precomputed 1/(t!(t+k)!)
// constants (no divisions). 7 terms: accurate to float for kappa up to ~8.
__global__ void precompute_fourier(const float* __restrict__ mu,
                                   const float* __restrict__ kappa,
                                   const float* __restrict__ weight,
                                   const float* __restrict__ ref_angles) {
    int idx = blockIdx.x * blockDim.x + threadIdx.x;
    if (idx >= NBINS * NFREQ) return;
    int b = idx / NFREQ;
    int f = idx % NFREQ;
    float C[7];
    #pragma unroll
    for (int i = 0; i < 7; i++) C[i] = 0.f;

    #pragma unroll
    for (int m = 0; m < NKERN; m++) {
        int off = (b * NFREQ + f) * NKERN + m;
        float kp = kappa[off];
        float w  = weight[off];
        float me = mu[off] + ref_angles[f];
        float h  = 0.5f * kp;
        float h2 = h * h;
        float ek = __expf(-kp);
        // Horner polynomials: I_k = h^k * P_k(h2)
        float P0 = fmaf(h2, fmaf(h2, fmaf(h2, fmaf(h2, fmaf(h2, fmaf(h2,
                    1.9290123e-6f, 6.9444444e-5f), 1.7361111e-3f), 2.7777778e-2f),
                    0.25f), 1.0f), 1.0f);
        float P1 = fmaf(h2, fmaf(h2, fmaf(h2, fmaf(h2, fmaf(h2, fmaf(h2,
                    2.7557319e-7f, 1.1574074e-5f), 3.4722222e-4f), 6.9444444e-3f),
                    8.3333333e-2f), 0.5f), 1.0f);
        float P2 = fmaf(h2, fmaf(h2, fmaf(h2, fmaf(h2, fmaf(h2, fmaf(h2,
                    3.4446e-8f, 1.6534392e-6f), 5.7870370e-5f), 1.3888889e-3f),
                    2.0833333e-2f), 1.6666667e-1f), 0.5f);
        float P3 = fmaf(h2, fmaf(h2, fmaf(h2, fmaf(h2, fmaf(h2, fmaf(h2,
                    3.83e-9f, 2.0667e-7f), 8.2671958e-6f), 2.3148148e-4f),
                    4.1666667e-3f), 4.1666667e-2f), 1.6666667e-1f);
        float I0 = P0;
        float I1 = h * P1;
        float I2 = h2 * P2;
        float I3 = h2 * h * P3;

        float cm, sm;
        __sincosf(me, &sm, &cm);
        float wek = w * ek;
        C[0] += wek * I0;
        float g1 = 2.f * wek * I1;
        C[1] += g1 * cm;
        C[2] += g1 * sm;
        float c2 = cm * cm - sm * sm;
        float s2 = 2.f * cm * sm;
        float g2 = 2.f * wek * I2;
        C[3] += g2 * c2;
        C[4] += g2 * s2;
        float c3 = c2 * cm - s2 * sm;
        float s3 = s2 * cm + c2 * sm;
        float g3 = 2.f * wek * I3;
        C[5] += g3 * c3;
        C[6] += g3 * s3;
    }
    float* gC = (float*)g_C4;
    #pragma unroll
    for (int c = 0; c < 7; c++)
        gC[(f * 7 + c) * NBINS + b] = C[c];
}

// dynamic smem (floats):
//   sl[28*128]                         @ 0      (3584)
//   union @ 3584:
//     phase 1/2: float4 X4[64*28]               (28672 B)
//     phase 3/4: w1T[128*66] | h[28*64] | b1w2[128]
#define OFF_U    (KPB * NBINS)                 // 3584
#define OFF_H    (OFF_U + 128 * 66)            // 3584 + 8448
#define OFF_B1W2 (OFF_H + KPB * MLPH)
#define SMEM_BYTES ((OFF_B1W2 + 2 * MLPH) * 4) // 55808

__global__ __launch_bounds__(TPB, 2)
void key_pruning_main(const float2* __restrict__ K2,
                      const int*    __restrict__ pos,
                      const float*  __restrict__ bias,
                      const float*  __restrict__ W1,      // [64][128]
                      const float*  __restrict__ b1,
                      const float*  __restrict__ W2,
                      const float*  __restrict__ b2,
                      const float*  __restrict__ araw,
                      float*        __restrict__ out,
                      int n) {
    extern __shared__ float sm[];
    float4* X4 = (float4*)(sm + OFF_U);

    const int tid  = threadIdx.x;
    const int warp = tid >> 5;
    const int lane = tid & 31;
    const int key0 = blockIdx.x * KPB;

    // ---- Phase 1: compact features {mag, 2*c1, x, y} ----
    for (int i = tid; i < KPB * NFREQ; i += TPB) {
        int kk = i / NFREQ;
        int f  = i & (NFREQ - 1);
        int key = key0 + kk; if (key >= n) key = n - 1;
        float2 v = K2[key * NFREQ + f];
        float r2 = fmaf(v.x, v.x, v.y * v.y);
        r2 = fmaxf(r2, 1e-30f);
        float rinv = rsqrtf(r2);
        float mag = r2 * rinv;
        float c1x2 = 2.f * v.x * rinv;
        X4[f * KPB + kk] = make_float4(mag, c1x2, v.x, v.y);
    }
    __syncthreads();

    // ---- Phase 2: logits GEMM. warp = 28 keys x 32 bins; f split across warp-halves.
    //      Thread: 7 keys x 4 bins (packed f32x2 bin-pairs). ----
    const int fbase = (warp >= 4) ? 32 : 0;
    const int wb    = (warp & 3) * 32;
    const int kq    = lane >> 3;
    const int b0    = wb + (lane & 7) * 4;   // thread bins b0..b0+3
    const int kbase = kq * 7;

    ull acc[14];
    #pragma unroll
    for (int i = 0; i < 14; i++) acc[i] = 0ull;

    const float* gC = (const float*)g_C4;

    for (int fo = 0; fo < 32; fo++) {
        int f = fbase + fo;
        const float* Cf = gC + f * 7 * NBINS + b0;
        ulonglong2 Cc[7];
        #pragma unroll
        for (int c = 0; c < 7; c++)
            Cc[c] = *(const ulonglong2*)(Cf + c * NBINS);
        #pragma unroll
        for (int j = 0; j < 7; j++) {
            float4 x = X4[f * KPB + kbase + j];
            float xs0 = x.x;                        // m
            float c1x2 = x.y;                       // 2*cos1
            float xs1 = x.z;                        // m*cos1
            float xs2 = x.w;                        // m*sin1
            float xs3 = fmaf(c1x2, xs1, -xs0);      // m*cos2
            float xs4 = c1x2 * xs2;                 // m*sin2
            float xs5 = fmaf(c1x2, xs3, -xs1);      // m*cos3
            float xs6 = fmaf(c1x2, xs4, -xs2);      // m*sin3
            ull* a = &acc[2 * j];
            #define STEP(c, v) { ull d = dup2(v); fma2(a[0], d, Cc[c].x); fma2(a[1], d, Cc[c].y); }
            STEP(0, xs0) STEP(1, xs1) STEP(2, xs2) STEP(3, xs3)
            STEP(4, xs4) STEP(5, xs5) STEP(6, xs6)
            #undef STEP
        }
    }

    // f-split reduction into sl (low-f warps write with bias; high-f warps add)
    float4 bias4 = *(const float4*)&bias[b0];
    if (warp < 4) {
        #pragma unroll
        for (int j = 0; j < 7; j++) {
            float2 p0 = unpack2(acc[2 * j]);
            float2 p1 = unpack2(acc[2 * j + 1]);
            float4 o = make_float4(p0.x + bias4.x, p0.y + bias4.y,
                                   p1.x + bias4.z, p1.y + bias4.w);
            *(float4*)&sm[(kbase + j) * NBINS + b0] = o;
        }
    }
    __syncthreads();
    if (warp >= 4) {
        #pragma unroll
        for (int j = 0; j < 7; j++) {
            float2 p0 = unpack2(acc[2 * j]);
            float2 p1 = unpack2(acc[2 * j + 1]);
            float4 cur = *(float4*)&sm[(kbase + j) * NBINS + b0];
            cur.x += p0.x; cur.y += p0.y; cur.z += p1.x; cur.w += p1.y;
            *(float4*)&sm[(kbase + j) * NBINS + b0] = cur;
        }
    } else {
        // ---- Phase 3 (overlapped): stage transposed W1 [k][h], stride 66 ----
        for (int i = tid; i < MLPH * NBINS; i += 128) {
            int h = i >> 7;
            int k = i & 127;
            sm[OFF_U + k * 66 + h] = W1[i];
        }
        if (tid < MLPH) {
            sm[OFF_B1W2 + tid]        = b1[tid];
            sm[OFF_B1W2 + MLPH + tid] = W2[tid];
        }
    }
    __syncthreads();

    // ---- Phase 4: MLP layer 1 on 128 threads: 7 keys x 2 hidden per thread ----
    if (tid < 128) {
        int pkq = tid >> 5;            // key quarter (uniform per warp)
        int hb  = (tid & 31) * 2;      // hidden pair
        float a[7][2];
        #pragma unroll
        for (int j = 0; j < 7; j++) { a[j][0] = 0.f; a[j][1] = 0.f; }
        #pragma unroll 4
        for (int k = 0; k < NBINS; k++) {
            float2 w = *(const float2*)&sm[OFF_U + k * 66 + hb];
            #pragma unroll
            for (int j = 0; j < 7; j++) {
                float l = sm[(pkq * 7 + j) * NBINS + k];
                a[j][0] = fmaf(l, w.x, a[j][0]);
                a[j][1] = fmaf(l, w.y, a[j][1]);
            }
        }
        float bb0 = sm[OFF_B1W2 + hb],        bb1 = sm[OFF_B1W2 + hb + 1];
        float w20 = sm[OFF_B1W2 + MLPH + hb], w21 = sm[OFF_B1W2 + MLPH + hb + 1];
        #pragma unroll
        for (int j = 0; j < 7; j++) {
            float h0 = fmaxf(a[j][0] + bb0, 0.f) * w20;
            float h1 = fmaxf(a[j][1] + bb1, 0.f) * w21;
            *(float2*)&sm[OFF_H + (pkq * 7 + j) * MLPH + hb] = make_float2(h0, h1);
        }
    }
    __syncthreads();

    // ---- Phase 5: reduce, position weight, sigmoid ----
    if (tid < KPB && (key0 + tid) < n) {
        float s = b2[0];
        const float4* hp = (const float4*)&sm[OFF_H + tid * MLPH];
        float s1 = 0.f, s2 = 0.f, s3 = 0.f;
        #pragma unroll
        for (int j = 0; j < MLPH / 4; j++) {
            float4 v = hp[j];
            s += v.x; s1 += v.y; s2 += v.z; s3 += v.w;
        }
        s = (s + s1) + (s2 + s3);

        int p = pos[key0 + tid];
        float lp = log10f(fmaxf((float)p, 1.0f));
        float a0 = log1pf(expf(araw[0]));
        float a1 = log1pf(expf(araw[1]));
        float a2 = log1pf(expf(araw[2]));
        float w;
        if (lp < 3.f)      w = a0;
        else if (lp < 4.f) w = a0 + (a1 - a0) * (lp - 3.f);
        else if (lp < 5.f) w = a1 + (a2 - a1) * (lp - 4.f);
        else               w = a2;

        float z = s * w;
        out[key0 + tid] = 1.f / (1.f + expf(-z));
    }
}

extern "C" void kernel_launch(void* const* d_in, const int* in_sizes, int n_in,
                              void* d_out, int out_size) {
    const float* K      = (const float*)d_in[0];
    const int*   pos    = (const int*)  d_in[1];
    const float* ra     = (const float*)d_in[2];
    const float* mu     = (const float*)d_in[3];
    const float* kappa  = (const float*)d_in[4];
    const float* weight = (const float*)d_in[5];
    const float* bias   = (const float*)d_in[6];
    const float* W1     = (const float*)d_in[7];
    const float* b1     = (const float*)d_in[8];
    const float* W2     = (const float*)d_in[9];
    const float* b2     = (const float*)d_in[10];
    const float* araw   = (const float*)d_in[11];

    int n = in_sizes[1];   // number of keys

    static int smem_set = 0;
    if (!smem_set) {
        cudaFuncSetAttribute(key_pruning_main,
                             cudaFuncAttributeMaxDynamicSharedMemorySize, SMEM_BYTES);
        smem_set = 1;
    }

    precompute_fourier<<<(NBINS * NFREQ + 127) / 128, 128>>>(mu, kappa, weight, ra);

    int grid = (n + KPB - 1) / KPB;
    key_pruning_main<<<grid, TPB, SMEM_BYTES>>>((const float2*)K, pos, bias, W1, b1, W2, b2, araw,
                                                (float*)d_out, n);
}

// round 12
// speedup vs baseline: 2.1945x; 1.0009x over previous
#include <cuda_runtime.h>
#include <cuda_bf16.h>
#include <math.h>

#define NBINS 128
#define NFREQ 64
#define NKERN 3
#define MLPH  64
#define KPB   28   // keys per block -> grid 293; 2 blocks/SM
#define TPB   256

typedef unsigned long long ull;

// Planar coefficient table: g_C[f][coord][bin], coord 0..6 =
//   [A0, A1c, A1s, A2c, A2s, A3c, A3s]
// +1 f of zero padding so the prefetch pipeline can read one f past the end.
__device__ float4 g_C4[(NFREQ + 1) * 7 * NBINS / 4];

__device__ __forceinline__ void fma2(ull& acc, ull a, ull b) {
    asm("fma.rn.f32x2 %0, %1, %2, %0;" : "+l"(acc) : "l"(a), "l"(b));
}
__device__ __forceinline__ ull dup2(float v) {
    ull r;
    asm("mov.b64 %0, {%1, %1};" : "=l"(r) : "f"(v));
    return r;
}
__device__ __forceinline__ float2 unpack2(ull v) {
    float2 r;
    asm("mov.b64 {%0, %1}, %2;" : "=f"(r.x), "=f"(r.y) : "l"(v));
    return r;
}

// I_k(kappa) via Horner series in h2 = (kappa/2)^2, no divisions.
__global__ void precompute_fourier(const float* __restrict__ mu,
                                   const float* __restrict__ kappa,
                                   const float* __restrict__ weight,
                                   const float* __restrict__ ref_angles) {
    int idx = blockIdx.x * blockDim.x + threadIdx.x;
    if (idx >= NBINS * NFREQ) return;
    int b = idx / NFREQ;
    int f = idx % NFREQ;
    float C[7];
    #pragma unroll
    for (int i = 0; i < 7; i++) C[i] = 0.f;

    #pragma unroll
    for (int m = 0; m < NKERN; m++) {
        int off = (b * NFREQ + f) * NKERN + m;
        float kp = kappa[off];
        float w  = weight[off];
        float me = mu[off] + ref_angles[f];
        float h  = 0.5f * kp;
        float h2 = h * h;
        float ek = __expf(-kp);
        float P0 = fmaf(h2, fmaf(h2, fmaf(h2, fmaf(h2, fmaf(h2, fmaf(h2,
                    1.9290123e-6f, 6.9444444e-5f), 1.7361111e-3f), 2.7777778e-2f),
                    0.25f), 1.0f), 1.0f);
        float P1 = fmaf(h2, fmaf(h2, fmaf(h2, fmaf(h2, fmaf(h2, fmaf(h2,
                    2.7557319e-7f, 1.1574074e-5f), 3.4722222e-4f), 6.9444444e-3f),
                    8.3333333e-2f), 0.5f), 1.0f);
        float P2 = fmaf(h2, fmaf(h2, fmaf(h2, fmaf(h2, fmaf(h2, fmaf(h2,
                    3.4446e-8f, 1.6534392e-6f), 5.7870370e-5f), 1.3888889e-3f),
                    2.0833333e-2f), 1.6666667e-1f), 0.5f);
        float P3 = fmaf(h2, fmaf(h2, fmaf(h2, fmaf(h2, fmaf(h2, fmaf(h2,
                    3.83e-9f, 2.0667e-7f), 8.2671958e-6f), 2.3148148e-4f),
                    4.1666667e-3f), 4.1666667e-2f), 1.6666667e-1f);
        float I0 = P0;
        float I1 = h * P1;
        float I2 = h2 * P2;
        float I3 = h2 * h * P3;

        float cm, sm;
        __sincosf(me, &sm, &cm);
        float wek = w * ek;
        C[0] += wek * I0;
        float g1 = 2.f * wek * I1;
        C[1] += g1 * cm;
        C[2] += g1 * sm;
        float c2 = cm * cm - sm * sm;
        float s2 = 2.f * cm * sm;
        float g2 = 2.f * wek * I2;
        C[3] += g2 * c2;
        C[4] += g2 * s2;
        float c3 = c2 * cm - s2 * sm;
        float s3 = s2 * cm + c2 * sm;
        float g3 = 2.f * wek * I3;
        C[5] += g3 * c3;
        C[6] += g3 * s3;
    }
    float* gC = (float*)g_C4;
    #pragma unroll
    for (int c = 0; c < 7; c++)
        gC[(f * 7 + c) * NBINS + b] = C[c];
}

// dynamic smem (floats):
//   sl[28*128] @ 0  | union { X4[64*28] float4 | w1T[128*66]+h[28*64]+b1w2[128] }
#define OFF_U    (KPB * NBINS)                 // 3584
#define OFF_H    (OFF_U + 128 * 66)
#define OFF_B1W2 (OFF_H + KPB * MLPH)
#define SMEM_BYTES ((OFF_B1W2 + 2 * MLPH) * 4) // 55808

__global__ __launch_bounds__(TPB, 2)
void key_pruning_main(const float2* __restrict__ K2,
                      const int*    __restrict__ pos,
                      const float*  __restrict__ bias,
                      const float*  __restrict__ W1,      // [64][128]
                      const float*  __restrict__ b1,
                      const float*  __restrict__ W2,
                      const float*  __restrict__ b2,
                      const float*  __restrict__ araw,
                      float*        __restrict__ out,
                      int n) {
    extern __shared__ float sm[];
    float4* X4 = (float4*)(sm + OFF_U);

    const int tid  = threadIdx.x;
    const int warp = tid >> 5;
    const int lane = tid & 31;
    const int key0 = blockIdx.x * KPB;

    // ---- Phase 1: compact features {mag, 2*c1, x, y} ----
    for (int i = tid; i < KPB * NFREQ; i += TPB) {
        int kk = i / NFREQ;
        int f  = i & (NFREQ - 1);
        int key = key0 + kk; if (key >= n) key = n - 1;
        float2 v = K2[key * NFREQ + f];
        float r2 = fmaf(v.x, v.x, v.y * v.y);
        r2 = fmaxf(r2, 1e-30f);
        float rinv = rsqrtf(r2);
        float mag = r2 * rinv;
        float c1x2 = 2.f * v.x * rinv;
        X4[f * KPB + kk] = make_float4(mag, c1x2, v.x, v.y);
    }
    __syncthreads();

    // ---- Phase 2: logits GEMM with double-buffered C prefetch. ----
    const int fbase = (warp >= 4) ? 32 : 0;
    const int wb    = (warp & 3) * 32;
    const int kq    = lane >> 3;
    const int b0    = wb + (lane & 7) * 4;   // thread bins b0..b0+3
    const int kbase = kq * 7;

    ull acc[14];
    #pragma unroll
    for (int i = 0; i < 14; i++) acc[i] = 0ull;

    const float* gC = (const float*)g_C4;
    const float* Cf = gC + fbase * 7 * NBINS + b0;

    ulonglong2 CA[7], CB[7];
    #pragma unroll
    for (int c = 0; c < 7; c++)
        CA[c] = *(const ulonglong2*)(Cf + c * NBINS);

    #define COMPUTE(BUF, FIDX) do {                                           \
        const int _f = (FIDX);                                                \
        _Pragma("unroll")                                                     \
        for (int j = 0; j < 7; j++) {                                         \
            float4 x = X4[_f * KPB + kbase + j];                              \
            float xs0 = x.x;                                                  \
            float c1x2 = x.y;                                                 \
            float xs1 = x.z;                                                  \
            float xs2 = x.w;                                                  \
            float xs3 = fmaf(c1x2, xs1, -xs0);                                \
            float xs4 = c1x2 * xs2;                                           \
            float xs5 = fmaf(c1x2, xs3, -xs1);                                \
            float xs6 = fmaf(c1x2, xs4, -xs2);                                \
            ull* a = &acc[2 * j];                                             \
            { ull d = dup2(xs0); fma2(a[0], d, BUF[0].x); fma2(a[1], d, BUF[0].y); } \
            { ull d = dup2(xs1); fma2(a[0], d, BUF[1].x); fma2(a[1], d, BUF[1].y); } \
            { ull d = dup2(xs2); fma2(a[0], d, BUF[2].x); fma2(a[1], d, BUF[2].y); } \
            { ull d = dup2(xs3); fma2(a[0], d, BUF[3].x); fma2(a[1], d, BUF[3].y); } \
            { ull d = dup2(xs4); fma2(a[0], d, BUF[4].x); fma2(a[1], d, BUF[4].y); } \
            { ull d = dup2(xs5); fma2(a[0], d, BUF[5].x); fma2(a[1], d, BUF[5].y); } \
            { ull d = dup2(xs6); fma2(a[0], d, BUF[6].x); fma2(a[1], d, BUF[6].y); } \
        }                                                                     \
    } while (0)

    for (int fo = 0; fo < 32; fo += 2) {
        const float* Cn1 = Cf + 7 * NBINS;     // f+1
        #pragma unroll
        for (int c = 0; c < 7; c++)
            CB[c] = *(const ulonglong2*)(Cn1 + c * NBINS);
        COMPUTE(CA, fbase + fo);

        const float* Cn2 = Cf + 14 * NBINS;    // f+2 (padded table: safe at end)
        #pragma unroll
        for (int c = 0; c < 7; c++)
            CA[c] = *(const ulonglong2*)(Cn2 + c * NBINS);
        COMPUTE(CB, fbase + fo + 1);

        Cf = Cn2;
    }
    #undef COMPUTE

    // f-split reduction into sl (low-f warps write with bias; high-f warps add)
    float4 bias4 = *(const float4*)&bias[b0];
    if (warp < 4) {
        #pragma unroll
        for (int j = 0; j < 7; j++) {
            float2 p0 = unpack2(acc[2 * j]);
            float2 p1 = unpack2(acc[2 * j + 1]);
            float4 o = make_float4(p0.x + bias4.x, p0.y + bias4.y,
                                   p1.x + bias4.z, p1.y + bias4.w);
            *(float4*)&sm[(kbase + j) * NBINS + b0] = o;
        }
    }
    __syncthreads();
    if (warp >= 4) {
        #pragma unroll
        for (int j = 0; j < 7; j++) {
            float2 p0 = unpack2(acc[2 * j]);
            float2 p1 = unpack2(acc[2 * j + 1]);
            float4 cur = *(float4*)&sm[(kbase + j) * NBINS + b0];
            cur.x += p0.x; cur.y += p0.y; cur.z += p1.x; cur.w += p1.y;
            *(float4*)&sm[(kbase + j) * NBINS + b0] = cur;
        }
    } else {
        // ---- Phase 3 (overlapped): stage transposed W1 [k][h], stride 66 ----
        for (int i = tid; i < MLPH * NBINS; i += 128) {
            int h = i >> 7;
            int k = i & 127;
            sm[OFF_U + k * 66 + h] = W1[i];
        }
        if (tid < MLPH) {
            sm[OFF_B1W2 + tid]        = b1[tid];
            sm[OFF_B1W2 + MLPH + tid] = W2[tid];
        }
    }
    __syncthreads();

    // ---- Phase 4: MLP layer 1 on 128 threads: 7 keys x 2 hidden per thread ----
    if (tid < 128) {
        int pkq = tid >> 5;            // key quarter (uniform per warp)
        int hb  = (tid & 31) * 2;      // hidden pair
        float a[7][2];
        #pragma unroll
        for (int j = 0; j < 7; j++) { a[j][0] = 0.f; a[j][1] = 0.f; }
        #pragma unroll 4
        for (int k = 0; k < NBINS; k++) {
            float2 w = *(const float2*)&sm[OFF_U + k * 66 + hb];
            #pragma unroll
            for (int j = 0; j < 7; j++) {
                float l = sm[(pkq * 7 + j) * NBINS + k];
                a[j][0] = fmaf(l, w.x, a[j][0]);
                a[j][1] = fmaf(l, w.y, a[j][1]);
            }
        }
        float bb0 = sm[OFF_B1W2 + hb],        bb1 = sm[OFF_B1W2 + hb + 1];
        float w20 = sm[OFF_B1W2 + MLPH + hb], w21 = sm[OFF_B1W2 + MLPH + hb + 1];
        #pragma unroll
        for (int j = 0; j < 7; j++) {
            float h0 = fmaxf(a[j][0] + bb0, 0.f) * w20;
            float h1 = fmaxf(a[j][1] + bb1, 0.f) * w21;
            *(float2*)&sm[OFF_H + (pkq * 7 + j) * MLPH + hb] = make_float2(h0, h1);
        }
    }
    __syncthreads();

    // ---- Phase 5: reduce, position weight, sigmoid ----
    if (tid < KPB && (key0 + tid) < n) {
        float s = b2[0];
        const float4* hp = (const float4*)&sm[OFF_H + tid * MLPH];
        float s1 = 0.f, s2 = 0.f, s3 = 0.f;
        #pragma unroll
        for (int j = 0; j < MLPH / 4; j++) {
            float4 v = hp[j];
            s += v.x; s1 += v.y; s2 += v.z; s3 += v.w;
        }
        s = (s + s1) + (s2 + s3);

        int p = pos[key0 + tid];
        float lp = log10f(fmaxf((float)p, 1.0f));
        float a0 = log1pf(expf(araw[0]));
        float a1 = log1pf(expf(araw[1]));
        float a2 = log1pf(expf(araw[2]));
        float w;
        if (lp < 3.f)      w = a0;
        else if (lp < 4.f) w = a0 + (a1 - a0) * (lp - 3.f);
        else if (lp < 5.f) w = a1 + (a2 - a1) * (lp - 4.f);
        else               w = a2;

        float z = s * w;
        out[key0 + tid] = 1.f / (1.f + expf(-z));
    }
}

extern "C" void kernel_launch(void* const* d_in, const int* in_sizes, int n_in,
                              void* d_out, int out_size) {
    const float* K      = (const float*)d_in[0];
    const int*   pos    = (const int*)  d_in[1];
    const float* ra     = (const float*)d_in[2];
    const float* mu     = (const float*)d_in[3];
    const float* kappa  = (const float*)d_in[4];
    const float* weight = (const float*)d_in[5];
    const float* bias   = (const float*)d_in[6];
    const float* W1     = (const float*)d_in[7];
    const float* b1     = (const float*)d_in[8];
    const float* W2     = (const float*)d_in[9];
    const float* b2     = (const float*)d_in[10];
    const float* araw   = (const float*)d_in[11];

    int n = in_sizes[1];   // number of keys

    static int smem_set = 0;
    if (!smem_set) {
        cudaFuncSetAttribute(key_pruning_main,
                             cudaFuncAttributeMaxDynamicSharedMemorySize, SMEM_BYTES);
        smem_set = 1;
    }

    precompute_fourier<<<(NBINS * NFREQ + 127) / 128, 128>>>(mu, kappa, weight, ra);

    int grid = (n + KPB - 1) / KPB;
    key_pruning_main<<<grid, TPB, SMEM_BYTES>>>((const float2*)K, pos, bias, W1, b1, W2, b2, araw,
                                                (float*)d_out, n);
}